// round 7
// baseline (speedup 1.0000x reference)
#include <cuda_runtime.h>

// LTU_5918464934238: binary-threshold GEMV, one warp per row, 100% occupancy.
// out[i] = (W[i]·x + count(W[i]<0) < 2457.6) ? 0 : 1
//
// R7: grid=512 x 512thr (launch_bounds(512,4) -> 4 blocks/SM = 64 warps =
// full occupancy). 8192 warps == 8192 rows: one row per warp, zero inner
// barriers. W streamed with 4 front-batched LDG.128 per iteration; x read
// from smem (separate LDS pipe). Reduce = 5 shuffles at the very end.

#define LTU_THREADS 512
#define LTU_WPB     (LTU_THREADS / 32)   // 16 warps per block
#define LTU_VECS    1024                 // float4 per row

__global__ __launch_bounds__(LTU_THREADS, 4)
void ltu_kernel(const float* __restrict__ x,
                const float* __restrict__ W,
                float* __restrict__ out)
{
    __shared__ float4 xs[LTU_VECS];      // 16 KB

    const int tid  = threadIdx.x;
    const int lane = tid & 31;
    const int warp = tid >> 5;

    // Stage x once; the ONLY barrier in the kernel.
    const float4* __restrict__ xv = reinterpret_cast<const float4*>(x);
    for (int i = tid; i < LTU_VECS; i += LTU_THREADS)
        xs[i] = xv[i];
    __syncthreads();

    const int row = blockIdx.x * LTU_WPB + warp;      // exact: 8192 warps/rows
    const float4* __restrict__ Wr =
        reinterpret_cast<const float4*>(W) + (size_t)row * LTU_VECS;

    float    facc = 0.0f;
    unsigned cacc = 0u;

    #pragma unroll 1
    for (int j = 0; j < 8; j++) {
        const int base = lane + j * 128;

        // 4 front-batched LDG.128 (the DRAM stream)
        const float4 w0 = Wr[base];
        const float4 w1 = Wr[base + 32];
        const float4 w2 = Wr[base + 64];
        const float4 w3 = Wr[base + 96];
        // 4 LDS.128 (conflict-free: consecutive lanes -> consecutive float4)
        const float4 v0 = xs[base];
        const float4 v1 = xs[base + 32];
        const float4 v2 = xs[base + 64];
        const float4 v3 = xs[base + 96];

        float a0 = 0.f, a1 = 0.f, a2 = 0.f, a3 = 0.f;
        a0 = fmaf(w0.x, v0.x, a0); a1 = fmaf(w0.y, v0.y, a1);
        a2 = fmaf(w0.z, v0.z, a2); a3 = fmaf(w0.w, v0.w, a3);
        a0 = fmaf(w1.x, v1.x, a0); a1 = fmaf(w1.y, v1.y, a1);
        a2 = fmaf(w1.z, v1.z, a2); a3 = fmaf(w1.w, v1.w, a3);
        a0 = fmaf(w2.x, v2.x, a0); a1 = fmaf(w2.y, v2.y, a1);
        a2 = fmaf(w2.z, v2.z, a2); a3 = fmaf(w2.w, v2.w, a3);
        a0 = fmaf(w3.x, v3.x, a0); a1 = fmaf(w3.y, v3.y, a1);
        a2 = fmaf(w3.z, v3.z, a2); a3 = fmaf(w3.w, v3.w, a3);
        facc += (a0 + a1) + (a2 + a3);

        cacc +=
            (__float_as_uint(w0.x) >> 31) + (__float_as_uint(w0.y) >> 31) +
            (__float_as_uint(w0.z) >> 31) + (__float_as_uint(w0.w) >> 31) +
            (__float_as_uint(w1.x) >> 31) + (__float_as_uint(w1.y) >> 31) +
            (__float_as_uint(w1.z) >> 31) + (__float_as_uint(w1.w) >> 31) +
            (__float_as_uint(w2.x) >> 31) + (__float_as_uint(w2.y) >> 31) +
            (__float_as_uint(w2.z) >> 31) + (__float_as_uint(w2.w) >> 31) +
            (__float_as_uint(w3.x) >> 31) + (__float_as_uint(w3.y) >> 31) +
            (__float_as_uint(w3.z) >> 31) + (__float_as_uint(w3.w) >> 31);
    }

    float t = facc + (float)cacc;

    #pragma unroll
    for (int o = 16; o > 0; o >>= 1)
        t += __shfl_xor_sync(0xffffffffu, t, o);

    if (lane == 0) {
        const float tau_base = 0.6f * 4096.0f;        // 2457.60009765625
        out[row] = (t < tau_base) ? 0.0f : 1.0f;
    }
}

extern "C" void kernel_launch(void* const* d_in, const int* in_sizes, int n_in,
                              void* d_out, int out_size)
{
    const float* x = (const float*)d_in[0];
    const float* W = (const float*)d_in[1];
    if (n_in >= 2 && in_sizes[0] > in_sizes[1]) {
        x = (const float*)d_in[1];
        W = (const float*)d_in[0];
    }
    float* out = (float*)d_out;
    const int rows = out_size;            // 8192

    const int grid = rows / LTU_WPB;      // 512 blocks * 16 warps = 8192 rows
    ltu_kernel<<<grid, LTU_THREADS>>>(x, W, out);
}